// round 1
// baseline (speedup 1.0000x reference)
#include <cuda_runtime.h>

#define N_NODES 50000
#define N_EDGES 600000
#define D 128
#define BN_EPS 1e-5f

// ---------------- scratch (static device globals; no runtime alloc) ----------
__device__ float  g_agg[(size_t)N_NODES * D];   // 25.6 MB
__device__ float  g_h1 [(size_t)N_NODES * D];   // 25.6 MB
__device__ double g_sum[D];
__device__ double g_sumsq[D];

// ---------------- kernel 1: zero agg + BN accumulators ----------------------
__global__ void zero_kernel() {
    long long i = (long long)blockIdx.x * blockDim.x + threadIdx.x;
    const long long n4 = (long long)N_NODES * D / 4;
    if (i < n4) reinterpret_cast<float4*>(g_agg)[i] = make_float4(0.f, 0.f, 0.f, 0.f);
    if (i < D) { g_sum[i] = 0.0; g_sumsq[i] = 0.0; }
}

// ---------------- kernel 2: edge scatter  (1 warp per edge) -----------------
__global__ void edge_kernel(const float* __restrict__ x,
                            const int*   __restrict__ ei,
                            const float* __restrict__ ea) {
    int warp = (blockIdx.x * blockDim.x + threadIdx.x) >> 5;
    int lane = threadIdx.x & 31;
    if (warp >= N_EDGES) return;
    int src = ei[warp];
    int dst = ei[N_EDGES + warp];
    float4 a = reinterpret_cast<const float4*>(x  + (long long)src  * D)[lane];
    float4 b = reinterpret_cast<const float4*>(ea + (long long)warp * D)[lane];
    float4 m;
    m.x = fmaxf(a.x + b.x, 0.f);
    m.y = fmaxf(a.y + b.y, 0.f);
    m.z = fmaxf(a.z + b.z, 0.f);
    m.w = fmaxf(a.w + b.w, 0.f);
    float* dp = g_agg + (long long)dst * D + lane * 4;
    asm volatile("red.global.add.v4.f32 [%0], {%1, %2, %3, %4};"
                 :: "l"(dp), "f"(m.x), "f"(m.y), "f"(m.z), "f"(m.w) : "memory");
}

// ---------------- kernel 3/4: tiled fp32 GEMM  y = h @ W^T + b --------------
// Tile 128 rows x 128 cols per block, 256 threads, 8x8 microtile per thread.
// Both operands stored k-major in smem (stride 132 keeps 16B alignment).
#define SM_STRIDE 132
#define GEMM_SMEM (2 * 128 * SM_STRIDE * 4)

template <bool FIRST>  // FIRST: in = x + g_agg, out = relu(.) -> g_h1
                       // !FIRST: in = g_h1,   out = (.)      -> outext
__global__ void gemm_kernel(const float* __restrict__ Aext,
                            const float* __restrict__ W,
                            const float* __restrict__ bias,
                            float* __restrict__ outext) {
    extern __shared__ float sh[];
    float* WsT = sh;                        // [k=128][SM_STRIDE] holds W[o][k] at WsT[k][o]
    float* HsT = sh + 128 * SM_STRIDE;      // [k=128][SM_STRIDE] holds h[r][k] at HsT[k][r]
    const int t = threadIdx.x;
    const int row0 = blockIdx.x * 128;

    // load W transposed (coalesced gmem, stride-132 smem stores)
#pragma unroll
    for (int i = 0; i < 64; i++) {
        int idx = i * 256 + t;
        int o = idx >> 7, k = idx & 127;
        WsT[k * SM_STRIDE + o] = W[o * 128 + k];
    }
    // load A tile transposed
#pragma unroll
    for (int i = 0; i < 64; i++) {
        int idx = i * 256 + t;
        int r = idx >> 7, k = idx & 127;
        int row = row0 + r;
        float v = 0.f;
        if (row < N_NODES) {
            long long g = (long long)row * 128 + k;
            if (FIRST) v = Aext[g] + g_agg[g];
            else       v = g_h1[g];
        }
        HsT[k * SM_STRIDE + r] = v;
    }
    __syncthreads();

    const int tx = t & 15, ty = t >> 4;
    const int c0 = tx * 8, r0 = ty * 8;
    float acc[8][8];
#pragma unroll
    for (int i = 0; i < 8; i++)
#pragma unroll
        for (int j = 0; j < 8; j++) acc[i][j] = 0.f;

#pragma unroll 4
    for (int k = 0; k < 128; k++) {
        const float4* hp = reinterpret_cast<const float4*>(HsT + k * SM_STRIDE + r0);
        const float4* wp = reinterpret_cast<const float4*>(WsT + k * SM_STRIDE + c0);
        float4 a0 = hp[0], a1 = hp[1];
        float4 b0 = wp[0], b1 = wp[1];
        float av[8] = {a0.x, a0.y, a0.z, a0.w, a1.x, a1.y, a1.z, a1.w};
        float bv[8] = {b0.x, b0.y, b0.z, b0.w, b1.x, b1.y, b1.z, b1.w};
#pragma unroll
        for (int i = 0; i < 8; i++)
#pragma unroll
            for (int j = 0; j < 8; j++) acc[i][j] += av[i] * bv[j];
    }

    float bb[8];
#pragma unroll
    for (int j = 0; j < 8; j++) bb[j] = bias[c0 + j];

#pragma unroll
    for (int i = 0; i < 8; i++) {
        int row = row0 + r0 + i;
        if (row >= N_NODES) break;
        float o[8];
#pragma unroll
        for (int j = 0; j < 8; j++) {
            float v = acc[i][j] + bb[j];
            o[j] = FIRST ? fmaxf(v, 0.f) : v;
        }
        float* dst = (FIRST ? g_h1 : outext) + (long long)row * 128 + c0;
        reinterpret_cast<float4*>(dst)[0] = make_float4(o[0], o[1], o[2], o[3]);
        reinterpret_cast<float4*>(dst)[1] = make_float4(o[4], o[5], o[6], o[7]);
    }
}

// ---------------- kernel 5: per-column sum / sumsq (double accum) -----------
__global__ void bn_reduce(const float* __restrict__ h) {
    const int t = threadIdx.x;      // column 0..127
    const int rows_per_block = (N_NODES + gridDim.x - 1) / gridDim.x;
    int rbeg = blockIdx.x * rows_per_block;
    int rend = min(rbeg + rows_per_block, N_NODES);
    double s = 0.0, ss = 0.0;
    for (int r = rbeg; r < rend; r++) {
        float v = h[(long long)r * 128 + t];
        s += (double)v;
        ss += (double)v * (double)v;
    }
    atomicAdd(&g_sum[t], s);
    atomicAdd(&g_sumsq[t], ss);
}

// ---------------- kernel 6: BN normalize + relu (in place on d_out) ---------
__global__ void bn_finalize(float* __restrict__ h,
                            const float* __restrict__ w,
                            const float* __restrict__ b) {
    long long i = (long long)blockIdx.x * blockDim.x + threadIdx.x;
    const long long n4 = (long long)N_NODES * D / 4;
    if (i >= n4) return;
    int c0 = (int)(i & 31) * 4;
    float4 v = reinterpret_cast<float4*>(h)[i];
    float o[4] = {v.x, v.y, v.z, v.w};
    const double invN = 1.0 / (double)N_NODES;
#pragma unroll
    for (int j = 0; j < 4; j++) {
        int c = c0 + j;
        double mean = g_sum[c] * invN;
        double var  = g_sumsq[c] * invN - mean * mean;
        float rstd = rsqrtf((float)var + BN_EPS);
        float y = ((o[j] - (float)mean) * rstd) * w[c] + b[c];
        o[j] = fmaxf(y, 0.f);
    }
    reinterpret_cast<float4*>(h)[i] = make_float4(o[0], o[1], o[2], o[3]);
}

// ---------------- launcher ---------------------------------------------------
extern "C" void kernel_launch(void* const* d_in, const int* in_sizes, int n_in,
                              void* d_out, int out_size) {
    const float* x   = (const float*)d_in[0];
    const int*   ei  = (const int*)  d_in[1];
    const float* ea  = (const float*)d_in[2];
    const float* w1  = (const float*)d_in[3];
    const float* b1  = (const float*)d_in[4];
    const float* w2  = (const float*)d_in[5];
    const float* b2  = (const float*)d_in[6];
    const float* bnw = (const float*)d_in[7];
    const float* bnb = (const float*)d_in[8];
    float* out = (float*)d_out;

    cudaFuncSetAttribute(gemm_kernel<true>,  cudaFuncAttributeMaxDynamicSharedMemorySize, GEMM_SMEM);
    cudaFuncSetAttribute(gemm_kernel<false>, cudaFuncAttributeMaxDynamicSharedMemorySize, GEMM_SMEM);

    // 1. zero scratch
    zero_kernel<<<(N_NODES * D / 4 + 255) / 256, 256>>>();
    // 2. edge scatter: one warp per edge
    {
        long long threads = (long long)N_EDGES * 32;
        edge_kernel<<<(unsigned)((threads + 255) / 256), 256>>>(x, ei, ea);
    }
    // 3. h1 = relu((x+agg) @ w1^T + b1)
    const int ntiles = (N_NODES + 127) / 128;
    gemm_kernel<true ><<<ntiles, 256, GEMM_SMEM>>>(x, w1, b1, nullptr);
    // 4. h2 = h1 @ w2^T + b2  -> d_out
    gemm_kernel<false><<<ntiles, 256, GEMM_SMEM>>>(nullptr, w2, b2, out);
    // 5. column stats
    bn_reduce<<<250, 128>>>(out);
    // 6. normalize + relu in place
    bn_finalize<<<(N_NODES * D / 4 + 255) / 256, 256>>>(out, bnw, bnb);
}